// round 1
// baseline (speedup 1.0000x reference)
#include <cuda_runtime.h>
#include <cuda_bf16.h>
#include <stdint.h>

// Problem dims
#define B_    4096
#define S_    128
#define E_    1024
#define H1D   4096
#define H2D   2048
#define NCLS  3

// GEMM tiles
#define BM 128
#define BN 128
#define BK 64
#define GEMM_SMEM (2 * (BM + BN) * BK * 2)   // 65536 bytes (2 stages, bf16)

// ---------------- scratch (static device globals; no allocation) ----------------
__device__ __nv_bfloat16 g_X2[(size_t)B_ * 2 * E_];      // pooled activations [hi|lo]  (4096 x 2048)
__device__ __nv_bfloat16 g_T1[(size_t)H1D * 2 * E_];     // ternary w1 duplicated       (4096 x 2048)
__device__ float         g_Y1[(size_t)B_ * H1D];         // gemm1 out fp32              (4096 x 4096)
__device__ __nv_bfloat16 g_H1[(size_t)B_ * 2 * H1D];     // h1 [hi|lo]                  (4096 x 8192)
__device__ __nv_bfloat16 g_T2[(size_t)H2D * 2 * H1D];    // ternary w2 duplicated       (2048 x 8192)
__device__ float         g_Y2[(size_t)B_ * H2D];         // gemm2 out fp32              (4096 x 2048)
__device__ float         g_H2[(size_t)B_ * H2D];         // h2 fp32                     (4096 x 2048)
__device__ float         g_T3[NCLS * H2D];               // ternary w3 (fp32 {-1,0,1})
__device__ double        g_absum[3];
__device__ float         g_scales[3];

// ---------------- helpers ----------------
static __device__ __forceinline__ uint32_t smem_u32(const void* p) {
    return (uint32_t)__cvta_generic_to_shared(p);
}
static __device__ __forceinline__ void cp_async16(uint32_t s, const void* g) {
    asm volatile("cp.async.cg.shared.global [%0], [%1], 16;\n" :: "r"(s), "l"(g));
}

// ---------------- scale computation ----------------
__global__ void zero_kernel() {
    if (threadIdx.x < 3) g_absum[threadIdx.x] = 0.0;
}

__global__ void absum_kernel(const float* __restrict__ w, int n, int idx) {
    __shared__ double red[256];
    double s = 0.0;
    for (size_t i = (size_t)blockIdx.x * 256 + threadIdx.x; i < (size_t)n;
         i += (size_t)gridDim.x * 256)
        s += (double)fabsf(w[i]);
    red[threadIdx.x] = s;
    __syncthreads();
    for (int o = 128; o > 0; o >>= 1) {
        if (threadIdx.x < o) red[threadIdx.x] += red[threadIdx.x + o];
        __syncthreads();
    }
    if (threadIdx.x == 0) atomicAdd(&g_absum[idx], red[0]);
}

__global__ void finalize_kernel() {
    if (threadIdx.x == 0) {
        g_scales[0] = (float)(g_absum[0] / (double)((size_t)H1D * E_));
        g_scales[1] = (float)(g_absum[1] / (double)((size_t)H2D * H1D));
        g_scales[2] = (float)(g_absum[2] / (double)(NCLS * H2D));
    }
}

// ternary-quantize and write duplicated [t|t] bf16 weight buffer
__global__ void quant_dup_kernel(const float* __restrict__ w, int rows, int K, int sidx,
                                 __nv_bfloat16* __restrict__ td) {
    float inv = 1.0f / g_scales[sidx];
    int n = rows * K;
    for (int i = blockIdx.x * 256 + threadIdx.x; i < n; i += gridDim.x * 256) {
        int r = i / K, k = i - r * K;
        float t = rintf(fminf(fmaxf(w[i] * inv, -1.0f), 1.0f));   // round-half-even = jnp.round
        __nv_bfloat16 tb = __float2bfloat16(t);                    // {-1,0,1} exact in bf16
        td[(size_t)r * 2 * K + k]     = tb;
        td[(size_t)r * 2 * K + K + k] = tb;
    }
}

__global__ void quant3_kernel(const float* __restrict__ w3) {
    int i = blockIdx.x * 256 + threadIdx.x;
    if (i < NCLS * H2D) {
        float inv = 1.0f / g_scales[2];
        g_T3[i] = rintf(fminf(fmaxf(w3[i] * inv, -1.0f), 1.0f));
    }
}

// ---------------- embedding gather + masked mean pool ----------------
__global__ void pool_kernel(const int* __restrict__ ids, const float* __restrict__ emb) {
    __shared__ int sid[S_];
    __shared__ int scnt;
    int b = blockIdx.x, t = threadIdx.x;   // 256 threads
    if (t == 0) scnt = 0;
    __syncthreads();
    if (t < S_) {
        int id = ids[(size_t)b * S_ + t];
        sid[t] = id;
        if (id != 0) atomicAdd(&scnt, 1);
    }
    __syncthreads();
    int d = t * 4;
    float a0 = 0.f, a1 = 0.f, a2 = 0.f, a3 = 0.f;
    for (int s = 0; s < S_; s++) {
        int id = sid[s];
        if (id != 0) {
            float4 v = *(const float4*)(emb + (size_t)id * E_ + d);
            a0 += v.x; a1 += v.y; a2 += v.z; a3 += v.w;
        }
    }
    int c = scnt;
    float inv = 1.0f / (float)(c > 0 ? c : 1);
    float x[4] = {a0 * inv, a1 * inv, a2 * inv, a3 * inv};
    __nv_bfloat16* dst = g_X2 + (size_t)b * 2 * E_;
#pragma unroll
    for (int j = 0; j < 4; j++) {
        __nv_bfloat16 hi = __float2bfloat16(x[j]);
        __nv_bfloat16 lo = __float2bfloat16(x[j] - __bfloat162float(hi));
        dst[d + j]      = hi;
        dst[E_ + d + j] = lo;
    }
}

// ---------------- bf16 GEMM: C[M,N] = scale * (A[M,K] @ B[N,K]^T) + bias[n] ----------------
__global__ __launch_bounds__(256)
void gemm_bf16(const __nv_bfloat16* __restrict__ A,
               const __nv_bfloat16* __restrict__ Bm,
               const float* __restrict__ bias,
               int sidx,
               float* __restrict__ C, int M, int N, int K) {
    extern __shared__ __nv_bfloat16 sm[];
    const uint32_t As_u = smem_u32(sm);                         // 2 stages of BM x BK
    const uint32_t Bs_u = smem_u32(sm + 2 * BM * BK);           // 2 stages of BN x BK
    const int tid = threadIdx.x, lane = tid & 31, warp = tid >> 5;
    const int wm = warp & 1, wn = warp >> 1;                    // 2 x 4 warp grid
    const int bm = blockIdx.y * BM, bn = blockIdx.x * BN;
    const int KT = K / BK;

    float acc[4][4][4];
#pragma unroll
    for (int i = 0; i < 4; i++)
#pragma unroll
        for (int j = 0; j < 4; j++)
#pragma unroll
            for (int v = 0; v < 4; v++) acc[i][j][v] = 0.f;

    auto issue_load = [&](int stage, int kt) {
        const int k0 = kt * BK;
#pragma unroll
        for (int r = 0; r < 4; r++) {
            int idx = tid + r * 256;          // 0..1023
            int row = idx >> 3, c = idx & 7;  // 8 x 16B chunks per 128B row
            const __nv_bfloat16* g = A + (size_t)(bm + row) * K + k0 + c * 8;
            cp_async16(As_u + (stage * BM + row) * 128 + ((c ^ (row & 7)) << 4), g);
        }
#pragma unroll
        for (int r = 0; r < 4; r++) {
            int idx = tid + r * 256;
            int row = idx >> 3, c = idx & 7;
            const __nv_bfloat16* g = Bm + (size_t)(bn + row) * K + k0 + c * 8;
            cp_async16(Bs_u + (stage * BN + row) * 128 + ((c ^ (row & 7)) << 4), g);
        }
        asm volatile("cp.async.commit_group;\n");
    };

    issue_load(0, 0);

    for (int kt = 0; kt < KT; ++kt) {
        asm volatile("cp.async.wait_group 0;\n");
        __syncthreads();
        if (kt + 1 < KT) issue_load((kt + 1) & 1, kt + 1);
        const int st = kt & 1;
        const uint32_t Abase = As_u + (uint32_t)(st * BM) * 128;
        const uint32_t Bbase = Bs_u + (uint32_t)(st * BN) * 128;
#pragma unroll
        for (int kk = 0; kk < 4; ++kk) {
            uint32_t a[4][4];
#pragma unroll
            for (int i = 0; i < 4; i++) {
                int row = wm * 64 + i * 16 + (lane & 15);
                int c = kk * 2 + (lane >> 4);
                uint32_t addr = Abase + row * 128 + ((c ^ (row & 7)) << 4);
                asm volatile("ldmatrix.sync.aligned.m8n8.x4.shared.b16 {%0,%1,%2,%3}, [%4];\n"
                             : "=r"(a[i][0]), "=r"(a[i][1]), "=r"(a[i][2]), "=r"(a[i][3])
                             : "r"(addr));
            }
            uint32_t b[4][2];
#pragma unroll
            for (int j = 0; j < 4; j++) {
                int row = wn * 32 + j * 8 + (lane & 7);
                int c = kk * 2 + ((lane >> 3) & 1);
                uint32_t addr = Bbase + row * 128 + ((c ^ (row & 7)) << 4);
                asm volatile("ldmatrix.sync.aligned.m8n8.x2.shared.b16 {%0,%1}, [%2];\n"
                             : "=r"(b[j][0]), "=r"(b[j][1]) : "r"(addr));
            }
#pragma unroll
            for (int i = 0; i < 4; i++)
#pragma unroll
                for (int j = 0; j < 4; j++) {
                    asm volatile(
                        "mma.sync.aligned.m16n8k16.row.col.f32.bf16.bf16.f32 "
                        "{%0,%1,%2,%3}, {%4,%5,%6,%7}, {%8,%9}, {%0,%1,%2,%3};\n"
                        : "+f"(acc[i][j][0]), "+f"(acc[i][j][1]),
                          "+f"(acc[i][j][2]), "+f"(acc[i][j][3])
                        : "r"(a[i][0]), "r"(a[i][1]), "r"(a[i][2]), "r"(a[i][3]),
                          "r"(b[j][0]), "r"(b[j][1]));
                }
        }
    }

    const float s = g_scales[sidx];
#pragma unroll
    for (int i = 0; i < 4; i++)
#pragma unroll
        for (int j = 0; j < 4; j++) {
            int gm = bm + wm * 64 + i * 16 + (lane >> 2);
            int gn = bn + wn * 32 + j * 8 + (lane & 3) * 2;
            float b0 = bias[gn], b1 = bias[gn + 1];
            C[(size_t)gm * N + gn]           = acc[i][j][0] * s + b0;
            C[(size_t)gm * N + gn + 1]       = acc[i][j][1] * s + b1;
            C[(size_t)(gm + 8) * N + gn]     = acc[i][j][2] * s + b0;
            C[(size_t)(gm + 8) * N + gn + 1] = acc[i][j][3] * s + b1;
        }
}

// ---------------- LayerNorm + exact GELU ----------------
template <int NE>
__global__ void ln_gelu_kernel(const float* __restrict__ Y,
                               const float* __restrict__ gam,
                               const float* __restrict__ bet,
                               int N,
                               __nv_bfloat16* __restrict__ Hdup,   // [row][2N] hi|lo or null
                               float* __restrict__ Hf) {           // [row][N] fp32 or null
    __shared__ float red[256];
    int row = blockIdx.x, t = threadIdx.x;
    const float* y = Y + (size_t)row * N;
    float v[NE];
    float s = 0.f;
#pragma unroll
    for (int i = 0; i < NE; i++) { v[i] = y[t + i * 256]; s += v[i]; }
    red[t] = s; __syncthreads();
    for (int o = 128; o > 0; o >>= 1) { if (t < o) red[t] += red[t + o]; __syncthreads(); }
    float mu = red[0] / (float)N;
    __syncthreads();
    float q = 0.f;
#pragma unroll
    for (int i = 0; i < NE; i++) { float d = v[i] - mu; q += d * d; }
    red[t] = q; __syncthreads();
    for (int o = 128; o > 0; o >>= 1) { if (t < o) red[t] += red[t + o]; __syncthreads(); }
    float rstd = rsqrtf(red[0] / (float)N + 1e-5f);
#pragma unroll
    for (int i = 0; i < NE; i++) {
        int col = t + i * 256;
        float h = (v[i] - mu) * rstd * gam[col] + bet[col];
        float ge = 0.5f * h * (1.0f + erff(h * 0.70710678118654752440f));
        if (Hdup) {
            __nv_bfloat16 hi = __float2bfloat16(ge);
            __nv_bfloat16 lo = __float2bfloat16(ge - __bfloat162float(hi));
            Hdup[(size_t)row * 2 * N + col]     = hi;
            Hdup[(size_t)row * 2 * N + N + col] = lo;
        }
        if (Hf) Hf[(size_t)row * N + col] = ge;
    }
}

// ---------------- final tiny layer (fp32) ----------------
__global__ void final_kernel(const float* __restrict__ b3, float* __restrict__ out) {
    __shared__ float red[NCLS][128];
    int row = blockIdx.x, t = threadIdx.x;   // 128 threads
    const float* h = g_H2 + (size_t)row * H2D;
    float a0 = 0.f, a1 = 0.f, a2 = 0.f;
    for (int k = t; k < H2D; k += 128) {
        float hv = h[k];
        a0 += hv * g_T3[k];
        a1 += hv * g_T3[H2D + k];
        a2 += hv * g_T3[2 * H2D + k];
    }
    red[0][t] = a0; red[1][t] = a1; red[2][t] = a2;
    __syncthreads();
    for (int o = 64; o > 0; o >>= 1) {
        if (t < o) {
            red[0][t] += red[0][t + o];
            red[1][t] += red[1][t + o];
            red[2][t] += red[2][t + o];
        }
        __syncthreads();
    }
    if (t < NCLS) out[row * NCLS + t] = g_scales[2] * red[t][0] + b3[t];
}

// ---------------- launch ----------------
extern "C" void kernel_launch(void* const* d_in, const int* in_sizes, int n_in,
                              void* d_out, int out_size) {
    const int*   ids = (const int*)d_in[0];
    const float* emb = (const float*)d_in[1];
    const float* w1  = (const float*)d_in[2];
    const float* b1  = (const float*)d_in[3];
    const float* w2  = (const float*)d_in[4];
    const float* b2  = (const float*)d_in[5];
    const float* w3  = (const float*)d_in[6];
    const float* b3  = (const float*)d_in[7];
    const float* g1  = (const float*)d_in[8];
    const float* be1 = (const float*)d_in[9];
    const float* g2  = (const float*)d_in[10];
    const float* be2 = (const float*)d_in[11];
    float* out = (float*)d_out;

    void *pX2, *pT1, *pY1, *pH1, *pT2, *pY2, *pH2;
    cudaGetSymbolAddress(&pX2, g_X2);
    cudaGetSymbolAddress(&pT1, g_T1);
    cudaGetSymbolAddress(&pY1, g_Y1);
    cudaGetSymbolAddress(&pH1, g_H1);
    cudaGetSymbolAddress(&pT2, g_T2);
    cudaGetSymbolAddress(&pY2, g_Y2);
    cudaGetSymbolAddress(&pH2, g_H2);

    cudaFuncSetAttribute(gemm_bf16, cudaFuncAttributeMaxDynamicSharedMemorySize, GEMM_SMEM);

    // 1) per-tensor scales
    zero_kernel<<<1, 32>>>();
    absum_kernel<<<1024, 256>>>(w1, H1D * E_, 0);
    absum_kernel<<<1024, 256>>>(w2, H2D * H1D, 1);
    absum_kernel<<<32, 256>>>(w3, NCLS * H2D, 2);
    finalize_kernel<<<1, 32>>>();

    // 2) quantize weights (duplicated [t|t] along K for hi/lo trick)
    quant_dup_kernel<<<2048, 256>>>(w1, H1D, E_, 0, (__nv_bfloat16*)pT1);
    quant_dup_kernel<<<4096, 256>>>(w2, H2D, H1D, 1, (__nv_bfloat16*)pT2);
    quant3_kernel<<<(NCLS * H2D + 255) / 256, 256>>>(w3);

    // 3) embedding gather + masked mean pool -> X2 = [hi|lo]
    pool_kernel<<<B_, 256>>>(ids, emb);

    // 4) layer 1: Y1 = s1*(X2 @ T1^T) + b1 ; LN ; GELU -> H1 = [hi|lo]
    {
        dim3 grid(H1D / BN, B_ / BM);
        gemm_bf16<<<grid, 256, GEMM_SMEM>>>((const __nv_bfloat16*)pX2, (const __nv_bfloat16*)pT1,
                                            b1, 0, (float*)pY1, B_, H1D, 2 * E_);
    }
    ln_gelu_kernel<16><<<B_, 256>>>((const float*)pY1, g1, be1, H1D,
                                    (__nv_bfloat16*)pH1, nullptr);

    // 5) layer 2: Y2 = s2*(H1 @ T2^T) + b2 ; LN ; GELU -> H2 fp32
    {
        dim3 grid(H2D / BN, B_ / BM);
        gemm_bf16<<<grid, 256, GEMM_SMEM>>>((const __nv_bfloat16*)pH1, (const __nv_bfloat16*)pT2,
                                            b2, 1, (float*)pY2, B_, H2D, 2 * H1D);
    }
    ln_gelu_kernel<8><<<B_, 256>>>((const float*)pY2, g2, be2, H2D,
                                   nullptr, (float*)pH2);

    // 6) final tiny layer
    final_kernel<<<B_, 128>>>(b3, out);
}